// round 6
// baseline (speedup 1.0000x reference)
#include <cuda_runtime.h>
#include <cuda_fp16.h>
#include <math.h>

#define NN 100000
#define NE 3200000
#define STRIDE 160        // bucket capacity per dst node (max in-degree bound)
#define FEPS 1e-16f
#define SLOPE 0.2f
#define FULL 0xffffffffu
#define QS 4096.0f
#define QSI (1.0f / 4096.0f)

// ---------------- scratch (device globals; no allocation allowed) ------------
__device__ uint4  g_rec1[NN];   // {x01 fp16x2, x23 fp16x2, as1_01 s16x2, as1_23 s16x2}
__device__ float4 g_ad1[NN];
__device__ float4 g_rec2[NN];   // {h2a, h2b, as2, ad2}
__device__ int    g_pos[NN];    // per-dst cursor == final count
__device__ int    g_srcs[(size_t)NN * STRIDE];
__device__ uint4  g_recb[(size_t)NN * STRIDE];   // bucketed per-edge records
__device__ float  g_As[16];     // As[k*4+h] = W1[:,hblk] @ a_s[h]
__device__ float  g_Ad[16];

// ---------------- tiny prep: fold a_src1/a_dst1 through W1 -------------------
__global__ void k_prep(const float* __restrict__ W1, const float* __restrict__ as1w,
                       const float* __restrict__ ad1w) {
    int t = threadIdx.x;
    if (t >= 16) return;
    int k = t >> 2, h = t & 3;
    float as = 0.f, ad = 0.f;
#pragma unroll
    for (int f = 0; f < 16; f++) {
        float wkj = W1[k * 64 + h * 16 + f];
        as += wkj * as1w[h * 16 + f];
        ad += wkj * ad1w[h * 16 + f];
    }
    g_As[t] = as;
    g_Ad[t] = ad;
}

__device__ __forceinline__ int q16(float v) {
    v = fminf(fmaxf(v * QS, -32767.f), 32767.f);
    return __float2int_rn(v);
}

// ---------------- node logits + record pack + self-loop seed -----------------
__global__ void k_node1(const float* __restrict__ x) {
    int n = blockIdx.x * blockDim.x + threadIdx.x;
    if (n >= NN) return;
    float4 xv = *reinterpret_cast<const float4*>(&x[n * 4]);
    float4 as, ad;
    as.x = xv.x * g_As[0] + xv.y * g_As[4] + xv.z * g_As[8]  + xv.w * g_As[12];
    as.y = xv.x * g_As[1] + xv.y * g_As[5] + xv.z * g_As[9]  + xv.w * g_As[13];
    as.z = xv.x * g_As[2] + xv.y * g_As[6] + xv.z * g_As[10] + xv.w * g_As[14];
    as.w = xv.x * g_As[3] + xv.y * g_As[7] + xv.z * g_As[11] + xv.w * g_As[15];
    ad.x = xv.x * g_Ad[0] + xv.y * g_Ad[4] + xv.z * g_Ad[8]  + xv.w * g_Ad[12];
    ad.y = xv.x * g_Ad[1] + xv.y * g_Ad[5] + xv.z * g_Ad[9]  + xv.w * g_Ad[13];
    ad.z = xv.x * g_Ad[2] + xv.y * g_Ad[6] + xv.z * g_Ad[10] + xv.w * g_Ad[14];
    ad.w = xv.x * g_Ad[3] + xv.y * g_Ad[7] + xv.z * g_Ad[11] + xv.w * g_Ad[15];
    g_ad1[n] = ad;
    uint4 r;
    __half2 hx01 = __floats2half2_rn(xv.x, xv.y);
    __half2 hx23 = __floats2half2_rn(xv.z, xv.w);
    r.x = *reinterpret_cast<unsigned*>(&hx01);
    r.y = *reinterpret_cast<unsigned*>(&hx23);
    r.z = (unsigned)(q16(as.x) & 0xffff) | ((unsigned)q16(as.y) << 16);
    r.w = (unsigned)(q16(as.z) & 0xffff) | ((unsigned)q16(as.w) << 16);
    g_rec1[n] = r;
    // self-loop pre-seeded in slot 0
    g_pos[n] = 1;
    g_srcs[(size_t)n * STRIDE] = n;
    g_recb[(size_t)n * STRIDE] = r;
}

// ---------------- bucketing: gather record + scatter into dst bucket ---------
// 8 edges/thread; high MLP, no dependent consumers -> pure throughput.
__global__ void k_bucket(const int* __restrict__ src, const int* __restrict__ dst) {
    int t = blockIdx.x * blockDim.x + threadIdx.x;
    if (t >= NE / 8) return;
    int4 sa = *reinterpret_cast<const int4*>(&src[t * 8]);
    int4 sb = *reinterpret_cast<const int4*>(&src[t * 8 + 4]);
    int4 da = *reinterpret_cast<const int4*>(&dst[t * 8]);
    int4 db = *reinterpret_cast<const int4*>(&dst[t * 8 + 4]);
    int ss[8] = {sa.x, sa.y, sa.z, sa.w, sb.x, sb.y, sb.z, sb.w};
    int dd[8] = {da.x, da.y, da.z, da.w, db.x, db.y, db.z, db.w};
    uint4 rr[8];
#pragma unroll
    for (int j = 0; j < 8; j++) rr[j] = g_rec1[ss[j]];     // batched gathers (MLP=8)
#pragma unroll
    for (int j = 0; j < 8; j++) {
        int p = atomicAdd(&g_pos[dd[j]], 1);
        if (p < STRIDE) {
            size_t slot = (size_t)dd[j] * STRIDE + p;
            g_srcs[slot] = ss[j];
            g_recb[slot] = rr[j];
        }
    }
}

// ---------------- layer 1 aggregation: warp per dst, lane per edge -----------
// Fully coalesced record reads. Accumulates t[h][k] = sum w_e^h x[src][k];
// epilogue projects through W1 and fuses normalize, +b1, ELU, W2, L2 logits.
__global__ void k_agg1(const float* __restrict__ W1, const float* __restrict__ b1,
                       const float* __restrict__ W2,
                       const float* __restrict__ as2w, const float* __restrict__ ad2w) {
    int d = (blockIdx.x * blockDim.x + threadIdx.x) >> 5;
    if (d >= NN) return;
    int lane = threadIdx.x & 31;
    size_t base = (size_t)d * STRIDE;
    int cnt = g_pos[d];
    if (cnt > STRIDE) cnt = STRIDE;
    float4 ad = g_ad1[d];

    float t00=0,t01=0,t02=0,t03=0, t10=0,t11=0,t12=0,t13=0;
    float t20=0,t21=0,t22=0,t23=0, t30=0,t31=0,t32=0,t33=0;
    float sd0=0, sd1=0, sd2=0, sd3=0;

    for (int i = lane; i < cnt; i += 32) {
        uint4 r = g_recb[base + i];                         // coalesced
        float2 x01 = __half22float2(*reinterpret_cast<__half2*>(&r.x));
        float2 x23 = __half22float2(*reinterpret_cast<__half2*>(&r.y));
        int q0 = (int)(short)(r.z & 0xffffu);
        int q1 = (int)r.z >> 16;
        int q2 = (int)(short)(r.w & 0xffffu);
        int q3 = (int)r.w >> 16;
        float v0 = fmaf((float)q0, QSI, ad.x);
        float v1 = fmaf((float)q1, QSI, ad.y);
        float v2 = fmaf((float)q2, QSI, ad.z);
        float v3 = fmaf((float)q3, QSI, ad.w);
        v0 = fmaxf(v0, SLOPE * v0);
        v1 = fmaxf(v1, SLOPE * v1);
        v2 = fmaxf(v2, SLOPE * v2);
        v3 = fmaxf(v3, SLOPE * v3);
        float w0 = __expf(v0), w1 = __expf(v1), w2 = __expf(v2), w3 = __expf(v3);
        sd0 += w0; sd1 += w1; sd2 += w2; sd3 += w3;
        t00 += w0*x01.x; t01 += w0*x01.y; t02 += w0*x23.x; t03 += w0*x23.y;
        t10 += w1*x01.x; t11 += w1*x01.y; t12 += w1*x23.x; t13 += w1*x23.y;
        t20 += w2*x01.x; t21 += w2*x01.y; t22 += w2*x23.x; t23 += w2*x23.y;
        t30 += w3*x01.x; t31 += w3*x01.y; t32 += w3*x23.x; t33 += w3*x23.y;
    }
#pragma unroll
    for (int o = 16; o; o >>= 1) {
        t00 += __shfl_xor_sync(FULL, t00, o); t01 += __shfl_xor_sync(FULL, t01, o);
        t02 += __shfl_xor_sync(FULL, t02, o); t03 += __shfl_xor_sync(FULL, t03, o);
        t10 += __shfl_xor_sync(FULL, t10, o); t11 += __shfl_xor_sync(FULL, t11, o);
        t12 += __shfl_xor_sync(FULL, t12, o); t13 += __shfl_xor_sync(FULL, t13, o);
        t20 += __shfl_xor_sync(FULL, t20, o); t21 += __shfl_xor_sync(FULL, t21, o);
        t22 += __shfl_xor_sync(FULL, t22, o); t23 += __shfl_xor_sync(FULL, t23, o);
        t30 += __shfl_xor_sync(FULL, t30, o); t31 += __shfl_xor_sync(FULL, t31, o);
        t32 += __shfl_xor_sync(FULL, t32, o); t33 += __shfl_xor_sync(FULL, t33, o);
        sd0 += __shfl_xor_sync(FULL, sd0, o); sd1 += __shfl_xor_sync(FULL, sd1, o);
        sd2 += __shfl_xor_sync(FULL, sd2, o); sd3 += __shfl_xor_sync(FULL, sd3, o);
    }
    int h = lane >> 3;                       // head for this lane's 2 features
    float th0, th1, th2, th3, sdh;
    if      (h == 0) { th0=t00; th1=t01; th2=t02; th3=t03; sdh=sd0; }
    else if (h == 1) { th0=t10; th1=t11; th2=t12; th3=t13; sdh=sd1; }
    else if (h == 2) { th0=t20; th1=t21; th2=t22; th3=t23; sdh=sd2; }
    else             { th0=t30; th1=t31; th2=t32; th3=t33; sdh=sd3; }
    float sinv = 1.f / (sdh + FEPS);

    int j0 = lane << 1, j1 = j0 + 1;
    float v0 = th0 * W1[j0] + th1 * W1[64 + j0] + th2 * W1[128 + j0] + th3 * W1[192 + j0];
    float v1 = th0 * W1[j1] + th1 * W1[64 + j1] + th2 * W1[128 + j1] + th3 * W1[192 + j1];
    v0 = v0 * sinv + b1[j0];
    v1 = v1 * sinv + b1[j1];
    v0 = (v0 > 0.f) ? v0 : (__expf(v0) - 1.f);   // ELU
    v1 = (v1 > 0.f) ? v1 : (__expf(v1) - 1.f);
    float pa = v0 * W2[j0 * 2]     + v1 * W2[j1 * 2];
    float pb = v0 * W2[j0 * 2 + 1] + v1 * W2[j1 * 2 + 1];
#pragma unroll
    for (int o = 16; o; o >>= 1) {
        pa += __shfl_xor_sync(FULL, pa, o);
        pb += __shfl_xor_sync(FULL, pb, o);
    }
    if (lane == 0) {
        float4 r;
        r.x = pa;
        r.y = pb;
        r.z = pa * as2w[0] + pb * as2w[1];
        r.w = pa * ad2w[0] + pb * ad2w[1];
        g_rec2[d] = r;
    }
}

// ---------------- layer 2 aggregation + log_softmax: warp per dst ------------
__global__ void k_agg2(const float* __restrict__ b2, float* __restrict__ out) {
    int d = (blockIdx.x * blockDim.x + threadIdx.x) >> 5;
    if (d >= NN) return;
    int lane = threadIdx.x & 31;
    size_t base = (size_t)d * STRIDE;
    int cnt = g_pos[d];
    if (cnt > STRIDE) cnt = STRIDE;
    float ad2d = g_rec2[d].w;               // broadcast

    float acc0 = 0.f, acc1 = 0.f, sden = 0.f;
    for (int i = lane; i < cnt; i += 32) {
        int s = g_srcs[base + i];
        float4 rr = g_rec2[s];
        float v = rr.z + ad2d;
        v = fmaxf(v, SLOPE * v);
        float w = __expf(v);
        acc0 += w * rr.x;
        acc1 += w * rr.y;
        sden += w;
    }
#pragma unroll
    for (int o = 16; o; o >>= 1) {
        acc0 += __shfl_xor_sync(FULL, acc0, o);
        acc1 += __shfl_xor_sync(FULL, acc1, o);
        sden += __shfl_xor_sync(FULL, sden, o);
    }
    if (lane == 0) {
        float inv = 1.f / (sden + FEPS);
        float v0 = acc0 * inv + b2[0];
        float v1 = acc1 * inv + b2[1];
        float mx = fmaxf(v0, v1);
        float lse = mx + logf(__expf(v0 - mx) + __expf(v1 - mx));
        out[d * 2]     = v0 - lse;
        out[d * 2 + 1] = v1 - lse;
    }
}

extern "C" void kernel_launch(void* const* d_in, const int* in_sizes, int n_in,
                              void* d_out, int out_size) {
    const float* x     = (const float*)d_in[0];
    const int*   ei    = (const int*)d_in[1];
    const float* W1    = (const float*)d_in[2];
    const float* asr1  = (const float*)d_in[3];
    const float* adst1 = (const float*)d_in[4];
    const float* b1    = (const float*)d_in[5];
    const float* W2    = (const float*)d_in[6];
    const float* asr2  = (const float*)d_in[7];
    const float* adst2 = (const float*)d_in[8];
    const float* b2    = (const float*)d_in[9];
    float* out = (float*)d_out;

    const int* src = ei;
    const int* dst = ei + NE;

    const int T = 256;
    int gN = (NN + T - 1) / T;
    int gB = (NE / 8 + T - 1) / T;
    int gW = (NN * 32 + T - 1) / T;    // warp-per-node kernels

    k_prep<<<1, 32>>>(W1, asr1, adst1);
    k_node1<<<gN, T>>>(x);
    k_bucket<<<gB, T>>>(src, dst);
    k_agg1<<<gW, T>>>(W1, b1, W2, asr2, adst2);
    k_agg2<<<gW, T>>>(b2, out);
}

// round 8
// speedup vs baseline: 1.2435x; 1.2435x over previous
#include <cuda_runtime.h>
#include <cuda_fp16.h>
#include <math.h>

#define NN 100000
#define NE 3200000
#define STRIDE 160        // bucket capacity per dst node (max in-degree bound)
#define FEPS 1e-16f
#define SLOPE 0.2f
#define FULL 0xffffffffu
#define QS 4096.0f
#define QSI (1.0f / 4096.0f)

// ---------------- scratch (device globals; no allocation allowed) ------------
__device__ uint4  g_rec1[NN];   // {x01 fp16x2, x23 fp16x2, as1_01 s16x2, as1_23 s16x2}
__device__ float  g_ad1[NN * 4];
__device__ float4 g_rec2[NN];   // {h2a, h2b, as2, ad2}
__device__ int    g_pos[NN];    // per-dst cursor == final count
__device__ int    g_srcs[(size_t)NN * STRIDE];
__device__ float  g_As[16];     // As[k*4+h] = W1[:,hblk] @ a_s[h]
__device__ float  g_Ad[16];

// ---------------- tiny prep: fold a_src1/a_dst1 through W1 -------------------
__global__ void k_prep(const float* __restrict__ W1, const float* __restrict__ as1w,
                       const float* __restrict__ ad1w) {
    int t = threadIdx.x;
    if (t >= 16) return;
    int k = t >> 2, h = t & 3;
    float as = 0.f, ad = 0.f;
#pragma unroll
    for (int f = 0; f < 16; f++) {
        float wkj = W1[k * 64 + h * 16 + f];
        as += wkj * as1w[h * 16 + f];
        ad += wkj * ad1w[h * 16 + f];
    }
    g_As[t] = as;
    g_Ad[t] = ad;
}

__device__ __forceinline__ int q16(float v) {
    v = fminf(fmaxf(v * QS, -32767.f), 32767.f);
    return __float2int_rn(v);
}

// ---------------- node logits + record pack + self-loop seed -----------------
__global__ void k_node1(const float* __restrict__ x) {
    int n = blockIdx.x * blockDim.x + threadIdx.x;
    if (n >= NN) return;
    g_pos[n] = 1;
    g_srcs[(size_t)n * STRIDE] = n;        // pre-seeded self loop
    float4 xv = *reinterpret_cast<const float4*>(&x[n * 4]);
    float4 as;
    as.x = xv.x * g_As[0] + xv.y * g_As[4] + xv.z * g_As[8]  + xv.w * g_As[12];
    as.y = xv.x * g_As[1] + xv.y * g_As[5] + xv.z * g_As[9]  + xv.w * g_As[13];
    as.z = xv.x * g_As[2] + xv.y * g_As[6] + xv.z * g_As[10] + xv.w * g_As[14];
    as.w = xv.x * g_As[3] + xv.y * g_As[7] + xv.z * g_As[11] + xv.w * g_As[15];
    g_ad1[n * 4 + 0] = xv.x * g_Ad[0] + xv.y * g_Ad[4] + xv.z * g_Ad[8]  + xv.w * g_Ad[12];
    g_ad1[n * 4 + 1] = xv.x * g_Ad[1] + xv.y * g_Ad[5] + xv.z * g_Ad[9]  + xv.w * g_Ad[13];
    g_ad1[n * 4 + 2] = xv.x * g_Ad[2] + xv.y * g_Ad[6] + xv.z * g_Ad[10] + xv.w * g_Ad[14];
    g_ad1[n * 4 + 3] = xv.x * g_Ad[3] + xv.y * g_Ad[7] + xv.z * g_Ad[11] + xv.w * g_Ad[15];
    uint4 r;
    __half2 hx01 = __floats2half2_rn(xv.x, xv.y);
    __half2 hx23 = __floats2half2_rn(xv.z, xv.w);
    r.x = *reinterpret_cast<unsigned*>(&hx01);
    r.y = *reinterpret_cast<unsigned*>(&hx23);
    r.z = (unsigned)(q16(as.x) & 0xffff) | ((unsigned)q16(as.y) << 16);
    r.w = (unsigned)(q16(as.z) & 0xffff) | ((unsigned)q16(as.w) << 16);
    g_rec1[n] = r;
}

// ---------------- single-pass bucketing (8 edges / thread) -------------------
__global__ void k_bucket(const int* __restrict__ src, const int* __restrict__ dst) {
    int t = blockIdx.x * blockDim.x + threadIdx.x;
    if (t >= NE / 8) return;
    int4 sa = *reinterpret_cast<const int4*>(&src[t * 8]);
    int4 sb = *reinterpret_cast<const int4*>(&src[t * 8 + 4]);
    int4 da = *reinterpret_cast<const int4*>(&dst[t * 8]);
    int4 db = *reinterpret_cast<const int4*>(&dst[t * 8 + 4]);
    int p;
    p = atomicAdd(&g_pos[da.x], 1); if (p < STRIDE) g_srcs[(size_t)da.x * STRIDE + p] = sa.x;
    p = atomicAdd(&g_pos[da.y], 1); if (p < STRIDE) g_srcs[(size_t)da.y * STRIDE + p] = sa.y;
    p = atomicAdd(&g_pos[da.z], 1); if (p < STRIDE) g_srcs[(size_t)da.z * STRIDE + p] = sa.z;
    p = atomicAdd(&g_pos[da.w], 1); if (p < STRIDE) g_srcs[(size_t)da.w * STRIDE + p] = sa.w;
    p = atomicAdd(&g_pos[db.x], 1); if (p < STRIDE) g_srcs[(size_t)db.x * STRIDE + p] = sb.x;
    p = atomicAdd(&g_pos[db.y], 1); if (p < STRIDE) g_srcs[(size_t)db.y * STRIDE + p] = sb.y;
    p = atomicAdd(&g_pos[db.z], 1); if (p < STRIDE) g_srcs[(size_t)db.z * STRIDE + p] = sb.z;
    p = atomicAdd(&g_pos[db.w], 1); if (p < STRIDE) g_srcs[(size_t)db.w * STRIDE + p] = sb.w;
}

// ---------------- layer 1 aggregation: warp per dst node ---------------------
// 8-lane group per head; lane u=lane&7 walks edges u, u+8, ... Four lanes
// sharing an edge read the same addresses (broadcast). Only 5 accumulators
// per lane; group-local 3-level reduction replaces the 20x5 shuffle tree.
__global__ void k_agg1(const float* __restrict__ W1, const float* __restrict__ b1,
                       const float* __restrict__ W2,
                       const float* __restrict__ as2w, const float* __restrict__ ad2w) {
    int d = (blockIdx.x * blockDim.x + threadIdx.x) >> 5;
    if (d >= NN) return;
    int lane = threadIdx.x & 31;
    int g = lane >> 3;                 // head owned by this 8-lane group
    int u = lane & 7;
    size_t base = (size_t)d * STRIDE;
    int cnt = g_pos[d];
    if (cnt > STRIDE) cnt = STRIDE;
    float adg = g_ad1[d * 4 + g];

    float t0 = 0.f, t1 = 0.f, t2 = 0.f, t3 = 0.f, sd = 0.f;
    for (int i = u; i < cnt; i += 8) {
        int s = g_srcs[base + i];
        uint4 r = g_rec1[s];
        float2 x01 = __half22float2(*reinterpret_cast<__half2*>(&r.x));
        float2 x23 = __half22float2(*reinterpret_cast<__half2*>(&r.y));
        unsigned qw = (g & 2) ? r.w : r.z;
        int q = (g & 1) ? ((int)qw >> 16) : (int)(short)(qw & 0xffffu);
        float v = fmaf((float)q, QSI, adg);
        v = fmaxf(v, SLOPE * v);
        float w = __expf(v);
        sd += w;
        t0 += w * x01.x; t1 += w * x01.y; t2 += w * x23.x; t3 += w * x23.y;
    }
    // 3-level reduction within the 8-lane group
#pragma unroll
    for (int o = 4; o; o >>= 1) {
        t0 += __shfl_xor_sync(FULL, t0, o);
        t1 += __shfl_xor_sync(FULL, t1, o);
        t2 += __shfl_xor_sync(FULL, t2, o);
        t3 += __shfl_xor_sync(FULL, t3, o);
        sd += __shfl_xor_sync(FULL, sd, o);
    }
    float sinv = 1.f / (sd + FEPS);

    int j0 = lane << 1, j1 = j0 + 1;   // features of head g
    float v0 = t0 * W1[j0] + t1 * W1[64 + j0] + t2 * W1[128 + j0] + t3 * W1[192 + j0];
    float v1 = t0 * W1[j1] + t1 * W1[64 + j1] + t2 * W1[128 + j1] + t3 * W1[192 + j1];
    v0 = v0 * sinv + b1[j0];
    v1 = v1 * sinv + b1[j1];
    v0 = (v0 > 0.f) ? v0 : (__expf(v0) - 1.f);   // ELU
    v1 = (v1 > 0.f) ? v1 : (__expf(v1) - 1.f);
    float pa = v0 * W2[j0 * 2]     + v1 * W2[j1 * 2];
    float pb = v0 * W2[j0 * 2 + 1] + v1 * W2[j1 * 2 + 1];
#pragma unroll
    for (int o = 16; o; o >>= 1) {
        pa += __shfl_xor_sync(FULL, pa, o);
        pb += __shfl_xor_sync(FULL, pb, o);
    }
    if (lane == 0) {
        float4 r;
        r.x = pa;
        r.y = pb;
        r.z = pa * as2w[0] + pb * as2w[1];
        r.w = pa * ad2w[0] + pb * ad2w[1];
        g_rec2[d] = r;
    }
}

// ---------------- layer 2 aggregation + log_softmax: warp per dst ------------
__global__ void k_agg2(const float* __restrict__ b2, float* __restrict__ out) {
    int d = (blockIdx.x * blockDim.x + threadIdx.x) >> 5;
    if (d >= NN) return;
    int lane = threadIdx.x & 31;
    size_t base = (size_t)d * STRIDE;
    int cnt = g_pos[d];
    if (cnt > STRIDE) cnt = STRIDE;
    float ad2d = g_rec2[d].w;               // broadcast

    float acc0 = 0.f, acc1 = 0.f, sden = 0.f;
    for (int i = lane; i < cnt; i += 32) {
        int s = g_srcs[base + i];
        float4 rr = g_rec2[s];
        float v = rr.z + ad2d;
        v = fmaxf(v, SLOPE * v);
        float w = __expf(v);
        acc0 += w * rr.x;
        acc1 += w * rr.y;
        sden += w;
    }
#pragma unroll
    for (int o = 16; o; o >>= 1) {
        acc0 += __shfl_xor_sync(FULL, acc0, o);
        acc1 += __shfl_xor_sync(FULL, acc1, o);
        sden += __shfl_xor_sync(FULL, sden, o);
    }
    if (lane == 0) {
        float inv = 1.f / (sden + FEPS);
        float v0 = acc0 * inv + b2[0];
        float v1 = acc1 * inv + b2[1];
        float mx = fmaxf(v0, v1);
        float lse = mx + logf(__expf(v0 - mx) + __expf(v1 - mx));
        out[d * 2]     = v0 - lse;
        out[d * 2 + 1] = v1 - lse;
    }
}

extern "C" void kernel_launch(void* const* d_in, const int* in_sizes, int n_in,
                              void* d_out, int out_size) {
    const float* x     = (const float*)d_in[0];
    const int*   ei    = (const int*)d_in[1];
    const float* W1    = (const float*)d_in[2];
    const float* asr1  = (const float*)d_in[3];
    const float* adst1 = (const float*)d_in[4];
    const float* b1    = (const float*)d_in[5];
    const float* W2    = (const float*)d_in[6];
    const float* asr2  = (const float*)d_in[7];
    const float* adst2 = (const float*)d_in[8];
    const float* b2    = (const float*)d_in[9];
    float* out = (float*)d_out;

    const int* src = ei;
    const int* dst = ei + NE;

    const int T = 256;
    int gN = (NN + T - 1) / T;
    int gB = (NE / 8 + T - 1) / T;
    int gW = (NN * 32 + T - 1) / T;    // warp-per-node kernels

    k_prep<<<1, 32>>>(W1, asr1, adst1);
    k_node1<<<gN, T>>>(x);
    k_bucket<<<gB, T>>>(src, dst);
    k_agg1<<<gW, T>>>(W1, b1, W2, asr2, adst2);
    k_agg2<<<gW, T>>>(b2, out);
}

// round 9
// speedup vs baseline: 1.2638x; 1.0163x over previous
#include <cuda_runtime.h>
#include <cuda_fp16.h>
#include <math.h>

#define NN 100000
#define NE 3200000
#define STRIDE 160        // bucket capacity per dst node (max in-degree bound)
#define FEPS 1e-16f
#define SLOPE 0.2f
#define FULL 0xffffffffu
#define QS 4096.0f
#define QSI (1.0f / 4096.0f)

// ---------------- scratch (device globals; no allocation allowed) ------------
__device__ uint4  g_rec1[NN];   // {x01 fp16x2, x23 fp16x2, as1_01 s16x2, as1_23 s16x2}
__device__ float  g_ad1[NN * 4];
__device__ float4 g_rec2[NN];   // {h2a, h2b, as2, ad2}
__device__ int    g_pos[NN];    // per-dst cursor == final count
__device__ int    g_srcs[(size_t)NN * STRIDE];

__device__ __forceinline__ int q16(float v) {
    v = fminf(fmaxf(v * QS, -32767.f), 32767.f);
    return __float2int_rn(v);
}

// ---------------- node logits + record pack + self-loop seed -----------------
// Folds a_src1/a_dst1 through W1 per-block in shared (cheap: 512 FMAs/block).
__global__ void k_node1(const float* __restrict__ x, const float* __restrict__ W1,
                        const float* __restrict__ as1w, const float* __restrict__ ad1w) {
    __shared__ float sAs[16], sAd[16];
    int t = threadIdx.x;
    if (t < 16) {
        int k = t >> 2, h = t & 3;
        float as = 0.f, ad = 0.f;
#pragma unroll
        for (int f = 0; f < 16; f++) {
            float wkj = W1[k * 64 + h * 16 + f];
            as += wkj * as1w[h * 16 + f];
            ad += wkj * ad1w[h * 16 + f];
        }
        sAs[t] = as;
        sAd[t] = ad;
    }
    __syncthreads();
    int n = blockIdx.x * blockDim.x + threadIdx.x;
    if (n >= NN) return;
    g_pos[n] = 1;
    g_srcs[(size_t)n * STRIDE] = n;        // pre-seeded self loop
    float4 xv = *reinterpret_cast<const float4*>(&x[n * 4]);
    float4 as;
    as.x = xv.x * sAs[0] + xv.y * sAs[4] + xv.z * sAs[8]  + xv.w * sAs[12];
    as.y = xv.x * sAs[1] + xv.y * sAs[5] + xv.z * sAs[9]  + xv.w * sAs[13];
    as.z = xv.x * sAs[2] + xv.y * sAs[6] + xv.z * sAs[10] + xv.w * sAs[14];
    as.w = xv.x * sAs[3] + xv.y * sAs[7] + xv.z * sAs[11] + xv.w * sAs[15];
    g_ad1[n * 4 + 0] = xv.x * sAd[0] + xv.y * sAd[4] + xv.z * sAd[8]  + xv.w * sAd[12];
    g_ad1[n * 4 + 1] = xv.x * sAd[1] + xv.y * sAd[5] + xv.z * sAd[9]  + xv.w * sAd[13];
    g_ad1[n * 4 + 2] = xv.x * sAd[2] + xv.y * sAd[6] + xv.z * sAd[10] + xv.w * sAd[14];
    g_ad1[n * 4 + 3] = xv.x * sAd[3] + xv.y * sAd[7] + xv.z * sAd[11] + xv.w * sAd[15];
    uint4 r;
    __half2 hx01 = __floats2half2_rn(xv.x, xv.y);
    __half2 hx23 = __floats2half2_rn(xv.z, xv.w);
    r.x = *reinterpret_cast<unsigned*>(&hx01);
    r.y = *reinterpret_cast<unsigned*>(&hx23);
    r.z = (unsigned)(q16(as.x) & 0xffff) | ((unsigned)q16(as.y) << 16);
    r.w = (unsigned)(q16(as.z) & 0xffff) | ((unsigned)q16(as.w) << 16);
    g_rec1[n] = r;
}

// ---------------- single-pass bucketing (8 edges / thread) -------------------
__global__ void k_bucket(const int* __restrict__ src, const int* __restrict__ dst) {
    int t = blockIdx.x * blockDim.x + threadIdx.x;
    if (t >= NE / 8) return;
    int4 sa = *reinterpret_cast<const int4*>(&src[t * 8]);
    int4 sb = *reinterpret_cast<const int4*>(&src[t * 8 + 4]);
    int4 da = *reinterpret_cast<const int4*>(&dst[t * 8]);
    int4 db = *reinterpret_cast<const int4*>(&dst[t * 8 + 4]);
    int p;
    p = atomicAdd(&g_pos[da.x], 1); if (p < STRIDE) g_srcs[(size_t)da.x * STRIDE + p] = sa.x;
    p = atomicAdd(&g_pos[da.y], 1); if (p < STRIDE) g_srcs[(size_t)da.y * STRIDE + p] = sa.y;
    p = atomicAdd(&g_pos[da.z], 1); if (p < STRIDE) g_srcs[(size_t)da.z * STRIDE + p] = sa.z;
    p = atomicAdd(&g_pos[da.w], 1); if (p < STRIDE) g_srcs[(size_t)da.w * STRIDE + p] = sa.w;
    p = atomicAdd(&g_pos[db.x], 1); if (p < STRIDE) g_srcs[(size_t)db.x * STRIDE + p] = sb.x;
    p = atomicAdd(&g_pos[db.y], 1); if (p < STRIDE) g_srcs[(size_t)db.y * STRIDE + p] = sb.y;
    p = atomicAdd(&g_pos[db.z], 1); if (p < STRIDE) g_srcs[(size_t)db.z * STRIDE + p] = sb.z;
    p = atomicAdd(&g_pos[db.w], 1); if (p < STRIDE) g_srcs[(size_t)db.w * STRIDE + p] = sb.w;
}

// per-edge work for k_agg1
#define PROC1(sidx)                                                            \
    {                                                                          \
        uint4 r = g_rec1[sidx];                                                \
        float2 x01 = __half22float2(*reinterpret_cast<__half2*>(&r.x));        \
        float2 x23 = __half22float2(*reinterpret_cast<__half2*>(&r.y));        \
        unsigned qw = (g & 2) ? r.w : r.z;                                     \
        int q = (g & 1) ? ((int)qw >> 16) : (int)(short)(qw & 0xffffu);        \
        float v = fmaf((float)q, QSI, adg);                                    \
        v = fmaxf(v, SLOPE * v);                                               \
        float w = __expf(v);                                                   \
        sd += w;                                                               \
        t0 += w * x01.x; t1 += w * x01.y; t2 += w * x23.x; t3 += w * x23.y;    \
    }

// ---------------- layer 1 aggregation: warp per dst node ---------------------
// 8-lane group per head. Indices for slots 0..63 prefetched with two coalesced
// loads and redistributed by shuffle -> all gathers issue with high MLP.
__global__ void k_agg1(const float* __restrict__ W1, const float* __restrict__ b1,
                       const float* __restrict__ W2,
                       const float* __restrict__ as2w, const float* __restrict__ ad2w) {
    int d = (blockIdx.x * blockDim.x + threadIdx.x) >> 5;
    if (d >= NN) return;
    int lane = threadIdx.x & 31;
    int g = lane >> 3;                 // head owned by this 8-lane group
    int u = lane & 7;
    size_t base = (size_t)d * STRIDE;
    int cnt = g_pos[d];                // warp-uniform
    if (cnt > STRIDE) cnt = STRIDE;
    float adg = g_ad1[d * 4 + g];

    int idxA = g_srcs[base + lane];    // slots 0..31 (coalesced)
    int idxB = 0;
    if (cnt > 32) idxB = g_srcs[base + 32 + lane];   // slots 32..63 (uniform branch)

    float t0 = 0.f, t1 = 0.f, t2 = 0.f, t3 = 0.f, sd = 0.f;
#pragma unroll
    for (int k = 0; k < 4; k++) {
        int i = u + 8 * k;
        int s = __shfl_sync(FULL, idxA, i);
        if (i < cnt) PROC1(s)
    }
    if (cnt > 32) {
#pragma unroll
        for (int k = 0; k < 4; k++) {
            int i = 32 + u + 8 * k;
            int s = __shfl_sync(FULL, idxB, i - 32);
            if (i < cnt) PROC1(s)
        }
        for (int i = 64 + u; i < cnt; i += 8) {      // vanishingly rare tail
            int s = g_srcs[base + i];
            PROC1(s)
        }
    }
    // 3-level reduction within the 8-lane group
#pragma unroll
    for (int o = 4; o; o >>= 1) {
        t0 += __shfl_xor_sync(FULL, t0, o);
        t1 += __shfl_xor_sync(FULL, t1, o);
        t2 += __shfl_xor_sync(FULL, t2, o);
        t3 += __shfl_xor_sync(FULL, t3, o);
        sd += __shfl_xor_sync(FULL, sd, o);
    }
    float sinv = 1.f / (sd + FEPS);

    int j0 = lane << 1, j1 = j0 + 1;   // features of head g
    float v0 = t0 * W1[j0] + t1 * W1[64 + j0] + t2 * W1[128 + j0] + t3 * W1[192 + j0];
    float v1 = t0 * W1[j1] + t1 * W1[64 + j1] + t2 * W1[128 + j1] + t3 * W1[192 + j1];
    v0 = v0 * sinv + b1[j0];
    v1 = v1 * sinv + b1[j1];
    v0 = (v0 > 0.f) ? v0 : (__expf(v0) - 1.f);   // ELU
    v1 = (v1 > 0.f) ? v1 : (__expf(v1) - 1.f);
    float pa = v0 * W2[j0 * 2]     + v1 * W2[j1 * 2];
    float pb = v0 * W2[j0 * 2 + 1] + v1 * W2[j1 * 2 + 1];
#pragma unroll
    for (int o = 16; o; o >>= 1) {
        pa += __shfl_xor_sync(FULL, pa, o);
        pb += __shfl_xor_sync(FULL, pb, o);
    }
    if (lane == 0) {
        float4 r;
        r.x = pa;
        r.y = pb;
        r.z = pa * as2w[0] + pb * as2w[1];
        r.w = pa * ad2w[0] + pb * ad2w[1];
        g_rec2[d] = r;
    }
}

// ---------------- layer 2 aggregation + log_softmax: warp per dst ------------
__global__ void k_agg2(const float* __restrict__ b2, float* __restrict__ out) {
    int d = (blockIdx.x * blockDim.x + threadIdx.x) >> 5;
    if (d >= NN) return;
    int lane = threadIdx.x & 31;
    size_t base = (size_t)d * STRIDE;
    int cnt = g_pos[d];
    if (cnt > STRIDE) cnt = STRIDE;
    float ad2d = g_rec2[d].w;               // broadcast

    float acc0 = 0.f, acc1 = 0.f, sden = 0.f;
    for (int i = lane; i < cnt; i += 32) {
        int s = g_srcs[base + i];
        float4 rr = g_rec2[s];
        float v = rr.z + ad2d;
        v = fmaxf(v, SLOPE * v);
        float w = __expf(v);
        acc0 += w * rr.x;
        acc1 += w * rr.y;
        sden += w;
    }
#pragma unroll
    for (int o = 16; o; o >>= 1) {
        acc0 += __shfl_xor_sync(FULL, acc0, o);
        acc1 += __shfl_xor_sync(FULL, acc1, o);
        sden += __shfl_xor_sync(FULL, sden, o);
    }
    if (lane == 0) {
        float inv = 1.f / (sden + FEPS);
        float v0 = acc0 * inv + b2[0];
        float v1 = acc1 * inv + b2[1];
        float mx = fmaxf(v0, v1);
        float lse = mx + logf(__expf(v0 - mx) + __expf(v1 - mx));
        out[d * 2]     = v0 - lse;
        out[d * 2 + 1] = v1 - lse;
    }
}

extern "C" void kernel_launch(void* const* d_in, const int* in_sizes, int n_in,
                              void* d_out, int out_size) {
    const float* x     = (const float*)d_in[0];
    const int*   ei    = (const int*)d_in[1];
    const float* W1    = (const float*)d_in[2];
    const float* asr1  = (const float*)d_in[3];
    const float* adst1 = (const float*)d_in[4];
    const float* b1    = (const float*)d_in[5];
    const float* W2    = (const float*)d_in[6];
    const float* asr2  = (const float*)d_in[7];
    const float* adst2 = (const float*)d_in[8];
    const float* b2    = (const float*)d_in[9];
    float* out = (float*)d_out;

    const int* src = ei;
    const int* dst = ei + NE;

    const int T = 256;
    int gN = (NN + T - 1) / T;
    int gB = (NE / 8 + T - 1) / T;
    int gW = (NN * 32 + T - 1) / T;    // warp-per-node kernels

    k_node1<<<gN, T>>>(x, W1, asr1, adst1);
    k_bucket<<<gB, T>>>(src, dst);
    k_agg1<<<gW, T>>>(W1, b1, W2, asr2, adst2);
    k_agg2<<<gW, T>>>(b2, out);
}

// round 10
// speedup vs baseline: 1.2851x; 1.0169x over previous
#include <cuda_runtime.h>
#include <cuda_fp16.h>
#include <math.h>

#define NN 100000
#define NE 3200000
#define STRIDE 160        // bucket capacity per dst node (max in-degree bound)
#define FEPS 1e-16f
#define SLOPE 0.2f
#define FULL 0xffffffffu
#define QS 4096.0f
#define QSI (1.0f / 4096.0f)

// ---------------- scratch (device globals; no allocation allowed) ------------
__device__ uint4  g_rec1[NN];   // {x01 fp16x2, x23 fp16x2, as1_01 s16x2, as1_23 s16x2}
__device__ float  g_ad1[NN * 4];
__device__ float4 g_rec2[NN];   // {h2a, h2b, as2, ad2}
__device__ int    g_pos[NN];    // per-dst cursor == final count
__device__ int    g_srcs[(size_t)NN * STRIDE];

__device__ __forceinline__ int q16(float v) {
    v = fminf(fmaxf(v * QS, -32767.f), 32767.f);
    return __float2int_rn(v);
}

// ---------------- node logits + record pack + self-loop seed -----------------
// Folds a_src1/a_dst1 through W1 per-block in shared (cheap: 512 FMAs/block).
__global__ void k_node1(const float* __restrict__ x, const float* __restrict__ W1,
                        const float* __restrict__ as1w, const float* __restrict__ ad1w) {
    __shared__ float sAs[16], sAd[16];
    int t = threadIdx.x;
    if (t < 16) {
        int k = t >> 2, h = t & 3;
        float as = 0.f, ad = 0.f;
#pragma unroll
        for (int f = 0; f < 16; f++) {
            float wkj = W1[k * 64 + h * 16 + f];
            as += wkj * as1w[h * 16 + f];
            ad += wkj * ad1w[h * 16 + f];
        }
        sAs[t] = as;
        sAd[t] = ad;
    }
    __syncthreads();
    int n = blockIdx.x * blockDim.x + threadIdx.x;
    if (n >= NN) return;
    g_pos[n] = 1;
    g_srcs[(size_t)n * STRIDE] = n;        // pre-seeded self loop
    float4 xv = *reinterpret_cast<const float4*>(&x[n * 4]);
    float4 as;
    as.x = xv.x * sAs[0] + xv.y * sAs[4] + xv.z * sAs[8]  + xv.w * sAs[12];
    as.y = xv.x * sAs[1] + xv.y * sAs[5] + xv.z * sAs[9]  + xv.w * sAs[13];
    as.z = xv.x * sAs[2] + xv.y * sAs[6] + xv.z * sAs[10] + xv.w * sAs[14];
    as.w = xv.x * sAs[3] + xv.y * sAs[7] + xv.z * sAs[11] + xv.w * sAs[15];
    g_ad1[n * 4 + 0] = xv.x * sAd[0] + xv.y * sAd[4] + xv.z * sAd[8]  + xv.w * sAd[12];
    g_ad1[n * 4 + 1] = xv.x * sAd[1] + xv.y * sAd[5] + xv.z * sAd[9]  + xv.w * sAd[13];
    g_ad1[n * 4 + 2] = xv.x * sAd[2] + xv.y * sAd[6] + xv.z * sAd[10] + xv.w * sAd[14];
    g_ad1[n * 4 + 3] = xv.x * sAd[3] + xv.y * sAd[7] + xv.z * sAd[11] + xv.w * sAd[15];
    uint4 r;
    __half2 hx01 = __floats2half2_rn(xv.x, xv.y);
    __half2 hx23 = __floats2half2_rn(xv.z, xv.w);
    r.x = *reinterpret_cast<unsigned*>(&hx01);
    r.y = *reinterpret_cast<unsigned*>(&hx23);
    r.z = (unsigned)(q16(as.x) & 0xffff) | ((unsigned)q16(as.y) << 16);
    r.w = (unsigned)(q16(as.z) & 0xffff) | ((unsigned)q16(as.w) << 16);
    g_rec1[n] = r;
}

// ---------------- single-pass bucketing (8 edges / thread) -------------------
// All 8 atomics issued first (MLP=8 on ATOMG return), then all 8 stores.
__global__ void k_bucket(const int* __restrict__ src, const int* __restrict__ dst) {
    int t = blockIdx.x * blockDim.x + threadIdx.x;
    if (t >= NE / 8) return;
    int4 sa = *reinterpret_cast<const int4*>(&src[t * 8]);
    int4 sb = *reinterpret_cast<const int4*>(&src[t * 8 + 4]);
    int4 da = *reinterpret_cast<const int4*>(&dst[t * 8]);
    int4 db = *reinterpret_cast<const int4*>(&dst[t * 8 + 4]);
    int ss[8] = {sa.x, sa.y, sa.z, sa.w, sb.x, sb.y, sb.z, sb.w};
    int dd[8] = {da.x, da.y, da.z, da.w, db.x, db.y, db.z, db.w};
    int p[8];
#pragma unroll
    for (int j = 0; j < 8; j++) p[j] = atomicAdd(&g_pos[dd[j]], 1);
#pragma unroll
    for (int j = 0; j < 8; j++)
        if (p[j] < STRIDE) g_srcs[(size_t)dd[j] * STRIDE + p[j]] = ss[j];
}

// per-edge work for k_agg1
#define PROC1(sidx)                                                            \
    {                                                                          \
        uint4 r = g_rec1[sidx];                                                \
        float2 x01 = __half22float2(*reinterpret_cast<__half2*>(&r.x));        \
        float2 x23 = __half22float2(*reinterpret_cast<__half2*>(&r.y));        \
        unsigned qw = (g & 2) ? r.w : r.z;                                     \
        int q = (g & 1) ? ((int)qw >> 16) : (int)(short)(qw & 0xffffu);        \
        float v = fmaf((float)q, QSI, adg);                                    \
        v = fmaxf(v, SLOPE * v);                                               \
        float w = __expf(v);                                                   \
        sd += w;                                                               \
        t0 += w * x01.x; t1 += w * x01.y; t2 += w * x23.x; t3 += w * x23.y;    \
    }

// ---------------- layer 1 aggregation: warp per dst node ---------------------
// 8-lane group per head. Indices for slots 0..63 prefetched with two coalesced
// loads and redistributed by shuffle -> all gathers issue with high MLP.
__global__ void k_agg1(const float* __restrict__ W1, const float* __restrict__ b1,
                       const float* __restrict__ W2,
                       const float* __restrict__ as2w, const float* __restrict__ ad2w) {
    int d = (blockIdx.x * blockDim.x + threadIdx.x) >> 5;
    if (d >= NN) return;
    int lane = threadIdx.x & 31;
    int g = lane >> 3;                 // head owned by this 8-lane group
    int u = lane & 7;
    size_t base = (size_t)d * STRIDE;
    int cnt = g_pos[d];                // warp-uniform
    if (cnt > STRIDE) cnt = STRIDE;
    float adg = g_ad1[d * 4 + g];

    int idxA = g_srcs[base + lane];    // slots 0..31 (coalesced)
    int idxB = 0;
    if (cnt > 32) idxB = g_srcs[base + 32 + lane];   // slots 32..63 (uniform branch)

    float t0 = 0.f, t1 = 0.f, t2 = 0.f, t3 = 0.f, sd = 0.f;
#pragma unroll
    for (int k = 0; k < 4; k++) {
        int i = u + 8 * k;
        int s = __shfl_sync(FULL, idxA, i);
        if (i < cnt) PROC1(s)
    }
    if (cnt > 32) {
#pragma unroll
        for (int k = 0; k < 4; k++) {
            int i = 32 + u + 8 * k;
            int s = __shfl_sync(FULL, idxB, i - 32);
            if (i < cnt) PROC1(s)
        }
        for (int i = 64 + u; i < cnt; i += 8) {      // vanishingly rare tail
            int s = g_srcs[base + i];
            PROC1(s)
        }
    }
    // 3-level reduction within the 8-lane group
#pragma unroll
    for (int o = 4; o; o >>= 1) {
        t0 += __shfl_xor_sync(FULL, t0, o);
        t1 += __shfl_xor_sync(FULL, t1, o);
        t2 += __shfl_xor_sync(FULL, t2, o);
        t3 += __shfl_xor_sync(FULL, t3, o);
        sd += __shfl_xor_sync(FULL, sd, o);
    }
    float sinv = 1.f / (sd + FEPS);

    int j0 = lane << 1, j1 = j0 + 1;   // features of head g
    float v0 = t0 * W1[j0] + t1 * W1[64 + j0] + t2 * W1[128 + j0] + t3 * W1[192 + j0];
    float v1 = t0 * W1[j1] + t1 * W1[64 + j1] + t2 * W1[128 + j1] + t3 * W1[192 + j1];
    v0 = v0 * sinv + b1[j0];
    v1 = v1 * sinv + b1[j1];
    v0 = (v0 > 0.f) ? v0 : (__expf(v0) - 1.f);   // ELU
    v1 = (v1 > 0.f) ? v1 : (__expf(v1) - 1.f);
    float pa = v0 * W2[j0 * 2]     + v1 * W2[j1 * 2];
    float pb = v0 * W2[j0 * 2 + 1] + v1 * W2[j1 * 2 + 1];
#pragma unroll
    for (int o = 16; o; o >>= 1) {
        pa += __shfl_xor_sync(FULL, pa, o);
        pb += __shfl_xor_sync(FULL, pb, o);
    }
    if (lane == 0) {
        float4 r;
        r.x = pa;
        r.y = pb;
        r.z = pa * as2w[0] + pb * as2w[1];
        r.w = pa * ad2w[0] + pb * ad2w[1];
        g_rec2[d] = r;
    }
}

// ---------------- layer 2 aggregation + log_softmax: warp per dst ------------
// Index loads and record gathers hoisted into independent predicated batches.
__global__ void k_agg2(const float* __restrict__ b2, float* __restrict__ out) {
    int d = (blockIdx.x * blockDim.x + threadIdx.x) >> 5;
    if (d >= NN) return;
    int lane = threadIdx.x & 31;
    size_t base = (size_t)d * STRIDE;
    int cnt = g_pos[d];                // warp-uniform
    if (cnt > STRIDE) cnt = STRIDE;
    float ad2d = g_rec2[d].w;          // broadcast

    bool pA = lane < cnt;
    bool pB = lane + 32 < cnt;
    int idxA = pA ? g_srcs[base + lane] : 0;
    int idxB = pB ? g_srcs[base + 32 + lane] : 0;
    float4 rA = {0.f, 0.f, 0.f, 0.f}, rB = {0.f, 0.f, 0.f, 0.f};
    if (pA) rA = g_rec2[idxA];         // independent gathers, issue together
    if (pB) rB = g_rec2[idxB];

    float acc0 = 0.f, acc1 = 0.f, sden = 0.f;
    if (pA) {
        float v = rA.z + ad2d;
        v = fmaxf(v, SLOPE * v);
        float w = __expf(v);
        acc0 += w * rA.x; acc1 += w * rA.y; sden += w;
    }
    if (pB) {
        float v = rB.z + ad2d;
        v = fmaxf(v, SLOPE * v);
        float w = __expf(v);
        acc0 += w * rB.x; acc1 += w * rB.y; sden += w;
    }
    if (cnt > 64) {
        for (int i = 64 + lane; i < cnt; i += 32) {   // vanishingly rare tail
            int s = g_srcs[base + i];
            float4 rr = g_rec2[s];
            float v = rr.z + ad2d;
            v = fmaxf(v, SLOPE * v);
            float w = __expf(v);
            acc0 += w * rr.x; acc1 += w * rr.y; sden += w;
        }
    }
#pragma unroll
    for (int o = 16; o; o >>= 1) {
        acc0 += __shfl_xor_sync(FULL, acc0, o);
        acc1 += __shfl_xor_sync(FULL, acc1, o);
        sden += __shfl_xor_sync(FULL, sden, o);
    }
    if (lane == 0) {
        float inv = 1.f / (sden + FEPS);
        float v0 = acc0 * inv + b2[0];
        float v1 = acc1 * inv + b2[1];
        float mx = fmaxf(v0, v1);
        float lse = mx + logf(__expf(v0 - mx) + __expf(v1 - mx));
        out[d * 2]     = v0 - lse;
        out[d * 2 + 1] = v1 - lse;
    }
}

extern "C" void kernel_launch(void* const* d_in, const int* in_sizes, int n_in,
                              void* d_out, int out_size) {
    const float* x     = (const float*)d_in[0];
    const int*   ei    = (const int*)d_in[1];
    const float* W1    = (const float*)d_in[2];
    const float* asr1  = (const float*)d_in[3];
    const float* adst1 = (const float*)d_in[4];
    const float* b1    = (const float*)d_in[5];
    const float* W2    = (const float*)d_in[6];
    const float* asr2  = (const float*)d_in[7];
    const float* adst2 = (const float*)d_in[8];
    const float* b2    = (const float*)d_in[9];
    float* out = (float*)d_out;

    const int* src = ei;
    const int* dst = ei + NE;

    const int T = 256;
    int gN = (NN + T - 1) / T;
    int gB = (NE / 8 + T - 1) / T;
    int gW = (NN * 32 + T - 1) / T;    // warp-per-node kernels

    k_node1<<<gN, T>>>(x, W1, asr1, adst1);
    k_bucket<<<gB, T>>>(src, dst);
    k_agg1<<<gW, T>>>(W1, b1, W2, asr2, adst2);
    k_agg2<<<gW, T>>>(b2, out);
}

// round 11
// speedup vs baseline: 1.3807x; 1.0744x over previous
#include <cuda_runtime.h>
#include <cuda_fp16.h>
#include <math.h>

#define NN 100000
#define NE 3200000
#define STRIDE 160        // bucket capacity per dst node (max real in-degree bound)
#define FEPS 1e-16f
#define SLOPE 0.2f
#define FULL 0xffffffffu
#define QS 4096.0f
#define QSI (1.0f / 4096.0f)

#define T 256
#define GB ((NE / 8 + T - 1) / T)     // edge-bucketing blocks
#define GN ((NN + T - 1) / T)         // node-prep blocks

// ---------------- scratch (device globals; no allocation allowed) ------------
// g_pos starts zeroed (BSS) and is re-zeroed by k_agg2 every run.
__device__ uint4  g_rec1[NN];   // {x01 fp16x2, x23 fp16x2, as1_01 s16x2, as1_23 s16x2}
__device__ float  g_ad1[NN * 4];
__device__ float4 g_rec2[NN];   // {h2a, h2b, as2, ad2}
__device__ int    g_pos[NN];    // per-dst cursor == real-edge count (no self loop)
__device__ int    g_srcs[(size_t)NN * STRIDE];

__device__ __forceinline__ int q16(float v) {
    v = fminf(fmaxf(v * QS, -32767.f), 32767.f);
    return __float2int_rn(v);
}

// ---------------- fused front: bucketing blocks + node-prep blocks -----------
// Blocks [0, GB): bucket 8 edges/thread (atomics batched, then stores).
// Blocks [GB, GB+GN): node logits + record pack. Independent work -> overlap.
__global__ void k_front(const int* __restrict__ src, const int* __restrict__ dst,
                        const float* __restrict__ x, const float* __restrict__ W1,
                        const float* __restrict__ as1w, const float* __restrict__ ad1w) {
    if (blockIdx.x < GB) {
        int t = blockIdx.x * T + threadIdx.x;
        if (t >= NE / 8) return;
        int4 sa = *reinterpret_cast<const int4*>(&src[t * 8]);
        int4 sb = *reinterpret_cast<const int4*>(&src[t * 8 + 4]);
        int4 da = *reinterpret_cast<const int4*>(&dst[t * 8]);
        int4 db = *reinterpret_cast<const int4*>(&dst[t * 8 + 4]);
        int ss[8] = {sa.x, sa.y, sa.z, sa.w, sb.x, sb.y, sb.z, sb.w};
        int dd[8] = {da.x, da.y, da.z, da.w, db.x, db.y, db.z, db.w};
        int p[8];
#pragma unroll
        for (int j = 0; j < 8; j++) p[j] = atomicAdd(&g_pos[dd[j]], 1);
#pragma unroll
        for (int j = 0; j < 8; j++)
            if (p[j] < STRIDE) g_srcs[(size_t)dd[j] * STRIDE + p[j]] = ss[j];
        return;
    }
    // ---- node-prep blocks ----
    __shared__ float sAs[16], sAd[16];
    int tt = threadIdx.x;
    if (tt < 16) {
        int k = tt >> 2, h = tt & 3;
        float as = 0.f, ad = 0.f;
#pragma unroll
        for (int f = 0; f < 16; f++) {
            float wkj = W1[k * 64 + h * 16 + f];
            as += wkj * as1w[h * 16 + f];
            ad += wkj * ad1w[h * 16 + f];
        }
        sAs[tt] = as;
        sAd[tt] = ad;
    }
    __syncthreads();
    int n = (blockIdx.x - GB) * T + threadIdx.x;
    if (n >= NN) return;
    float4 xv = *reinterpret_cast<const float4*>(&x[n * 4]);
    float4 as;
    as.x = xv.x * sAs[0] + xv.y * sAs[4] + xv.z * sAs[8]  + xv.w * sAs[12];
    as.y = xv.x * sAs[1] + xv.y * sAs[5] + xv.z * sAs[9]  + xv.w * sAs[13];
    as.z = xv.x * sAs[2] + xv.y * sAs[6] + xv.z * sAs[10] + xv.w * sAs[14];
    as.w = xv.x * sAs[3] + xv.y * sAs[7] + xv.z * sAs[11] + xv.w * sAs[15];
    g_ad1[n * 4 + 0] = xv.x * sAd[0] + xv.y * sAd[4] + xv.z * sAd[8]  + xv.w * sAd[12];
    g_ad1[n * 4 + 1] = xv.x * sAd[1] + xv.y * sAd[5] + xv.z * sAd[9]  + xv.w * sAd[13];
    g_ad1[n * 4 + 2] = xv.x * sAd[2] + xv.y * sAd[6] + xv.z * sAd[10] + xv.w * sAd[14];
    g_ad1[n * 4 + 3] = xv.x * sAd[3] + xv.y * sAd[7] + xv.z * sAd[11] + xv.w * sAd[15];
    uint4 r;
    __half2 hx01 = __floats2half2_rn(xv.x, xv.y);
    __half2 hx23 = __floats2half2_rn(xv.z, xv.w);
    r.x = *reinterpret_cast<unsigned*>(&hx01);
    r.y = *reinterpret_cast<unsigned*>(&hx23);
    r.z = (unsigned)(q16(as.x) & 0xffff) | ((unsigned)q16(as.y) << 16);
    r.w = (unsigned)(q16(as.z) & 0xffff) | ((unsigned)q16(as.w) << 16);
    g_rec1[n] = r;
}

// per-edge work for k_agg1
#define PROC1(sidx)                                                            \
    {                                                                          \
        uint4 r = g_rec1[sidx];                                                \
        float2 x01 = __half22float2(*reinterpret_cast<__half2*>(&r.x));        \
        float2 x23 = __half22float2(*reinterpret_cast<__half2*>(&r.y));        \
        unsigned qw = (g & 2) ? r.w : r.z;                                     \
        int q = (g & 1) ? ((int)qw >> 16) : (int)(short)(qw & 0xffffu);        \
        float v = fmaf((float)q, QSI, adg);                                    \
        v = fmaxf(v, SLOPE * v);                                               \
        float w = __expf(v);                                                   \
        sd += w;                                                               \
        t0 += w * x01.x; t1 += w * x01.y; t2 += w * x23.x; t3 += w * x23.y;    \
    }

// ---------------- layer 1 aggregation: warp per dst node ---------------------
// 8-lane group per head; self-loop handled inline (guarded broadcast PROC).
__global__ void k_agg1(const float* __restrict__ W1, const float* __restrict__ b1,
                       const float* __restrict__ W2,
                       const float* __restrict__ as2w, const float* __restrict__ ad2w) {
    int d = (blockIdx.x * blockDim.x + threadIdx.x) >> 5;
    if (d >= NN) return;
    int lane = threadIdx.x & 31;
    int g = lane >> 3;                 // head owned by this 8-lane group
    int u = lane & 7;
    size_t base = (size_t)d * STRIDE;
    int cnt = g_pos[d];                // warp-uniform; real edges only
    if (cnt > STRIDE) cnt = STRIDE;
    float adg = g_ad1[d * 4 + g];

    int idxA = g_srcs[base + lane];    // slots 0..31 (coalesced)
    int idxB = 0;
    if (cnt > 32) idxB = g_srcs[base + 32 + lane];   // slots 32..63 (uniform branch)

    float t0 = 0.f, t1 = 0.f, t2 = 0.f, t3 = 0.f, sd = 0.f;
    if (u == 0) PROC1(d)               // self loop (once per 8-lane group)
#pragma unroll
    for (int k = 0; k < 4; k++) {
        int i = u + 8 * k;
        int s = __shfl_sync(FULL, idxA, i);
        if (i < cnt) PROC1(s)
    }
    if (cnt > 32) {
#pragma unroll
        for (int k = 0; k < 4; k++) {
            int i = 32 + u + 8 * k;
            int s = __shfl_sync(FULL, idxB, i - 32);
            if (i < cnt) PROC1(s)
        }
        for (int i = 64 + u; i < cnt; i += 8) {      // vanishingly rare tail
            int s = g_srcs[base + i];
            PROC1(s)
        }
    }
    // 3-level reduction within the 8-lane group
#pragma unroll
    for (int o = 4; o; o >>= 1) {
        t0 += __shfl_xor_sync(FULL, t0, o);
        t1 += __shfl_xor_sync(FULL, t1, o);
        t2 += __shfl_xor_sync(FULL, t2, o);
        t3 += __shfl_xor_sync(FULL, t3, o);
        sd += __shfl_xor_sync(FULL, sd, o);
    }
    float sinv = 1.f / (sd + FEPS);

    int j0 = lane << 1, j1 = j0 + 1;   // features of head g
    float v0 = t0 * W1[j0] + t1 * W1[64 + j0] + t2 * W1[128 + j0] + t3 * W1[192 + j0];
    float v1 = t0 * W1[j1] + t1 * W1[64 + j1] + t2 * W1[128 + j1] + t3 * W1[192 + j1];
    v0 = v0 * sinv + b1[j0];
    v1 = v1 * sinv + b1[j1];
    v0 = (v0 > 0.f) ? v0 : (__expf(v0) - 1.f);   // ELU
    v1 = (v1 > 0.f) ? v1 : (__expf(v1) - 1.f);
    float pa = v0 * W2[j0 * 2]     + v1 * W2[j1 * 2];
    float pb = v0 * W2[j0 * 2 + 1] + v1 * W2[j1 * 2 + 1];
#pragma unroll
    for (int o = 16; o; o >>= 1) {
        pa += __shfl_xor_sync(FULL, pa, o);
        pb += __shfl_xor_sync(FULL, pb, o);
    }
    if (lane == 0) {
        float4 r;
        r.x = pa;
        r.y = pb;
        r.z = pa * as2w[0] + pb * as2w[1];
        r.w = pa * ad2w[0] + pb * ad2w[1];
        g_rec2[d] = r;
    }
}

// ---------------- layer 2 aggregation + log_softmax: 16 lanes per dst --------
// Two nodes per warp; self-loop free (rec2[d] already in registers).
// Resets g_pos for the next graph replay.
__global__ void k_agg2(const float* __restrict__ b2, float* __restrict__ out) {
    int w = (blockIdx.x * blockDim.x + threadIdx.x) >> 5;
    int lane = threadIdx.x & 31;
    int half = lane >> 4;
    int u = lane & 15;
    int d = w * 2 + half;
    if (d >= NN) return;
    size_t base = (size_t)d * STRIDE;
    int cnt = g_pos[d];                // half-warp-uniform; real edges only
    if (cnt > STRIDE) cnt = STRIDE;
    float4 rd = g_rec2[d];             // broadcast within half
    float ad2d = rd.w;

    float acc0 = 0.f, acc1 = 0.f, sden = 0.f;
    // self loop (once per node)
    if (u == 0) {
        float v = rd.z + ad2d;
        v = fmaxf(v, SLOPE * v);
        float wt = __expf(v);
        acc0 += wt * rd.x; acc1 += wt * rd.y; sden += wt;
    }
    // three predicated batches cover slots 0..47 (deg ~ Poisson(32))
    bool p0 = u < cnt, p1 = u + 16 < cnt, p2 = u + 32 < cnt;
    int i0 = p0 ? g_srcs[base + u] : 0;
    int i1 = p1 ? g_srcs[base + 16 + u] : 0;
    int i2 = p2 ? g_srcs[base + 32 + u] : 0;
    float4 r0 = {0,0,0,0}, r1 = {0,0,0,0}, r2 = {0,0,0,0};
    if (p0) r0 = g_rec2[i0];
    if (p1) r1 = g_rec2[i1];
    if (p2) r2 = g_rec2[i2];
    if (p0) {
        float v = r0.z + ad2d; v = fmaxf(v, SLOPE * v);
        float wt = __expf(v);
        acc0 += wt * r0.x; acc1 += wt * r0.y; sden += wt;
    }
    if (p1) {
        float v = r1.z + ad2d; v = fmaxf(v, SLOPE * v);
        float wt = __expf(v);
        acc0 += wt * r1.x; acc1 += wt * r1.y; sden += wt;
    }
    if (p2) {
        float v = r2.z + ad2d; v = fmaxf(v, SLOPE * v);
        float wt = __expf(v);
        acc0 += wt * r2.x; acc1 += wt * r2.y; sden += wt;
    }
    if (cnt > 48) {
        for (int i = 48 + u; i < cnt; i += 16) {     // rare tail
            int s = g_srcs[base + i];
            float4 rr = g_rec2[s];
            float v = rr.z + ad2d; v = fmaxf(v, SLOPE * v);
            float wt = __expf(v);
            acc0 += wt * rr.x; acc1 += wt * rr.y; sden += wt;
        }
    }
    // 4-level reduction within the 16-lane half
#pragma unroll
    for (int o = 8; o; o >>= 1) {
        acc0 += __shfl_xor_sync(FULL, acc0, o);
        acc1 += __shfl_xor_sync(FULL, acc1, o);
        sden += __shfl_xor_sync(FULL, sden, o);
    }
    if (u == 0) {
        float inv = 1.f / (sden + FEPS);
        float v0 = acc0 * inv + b2[0];
        float v1 = acc1 * inv + b2[1];
        float mx = fmaxf(v0, v1);
        float lse = mx + logf(__expf(v0 - mx) + __expf(v1 - mx));
        out[d * 2]     = v0 - lse;
        out[d * 2 + 1] = v1 - lse;
        g_pos[d] = 0;                  // restore invariant for next replay
    }
}

extern "C" void kernel_launch(void* const* d_in, const int* in_sizes, int n_in,
                              void* d_out, int out_size) {
    const float* x     = (const float*)d_in[0];
    const int*   ei    = (const int*)d_in[1];
    const float* W1    = (const float*)d_in[2];
    const float* asr1  = (const float*)d_in[3];
    const float* adst1 = (const float*)d_in[4];
    const float* b1    = (const float*)d_in[5];
    const float* W2    = (const float*)d_in[6];
    const float* asr2  = (const float*)d_in[7];
    const float* adst2 = (const float*)d_in[8];
    const float* b2    = (const float*)d_in[9];
    float* out = (float*)d_out;

    const int* src = ei;
    const int* dst = ei + NE;

    int gW1 = (NN * 32 + T - 1) / T;        // warp-per-node (agg1)
    int gW2 = (NN * 16 + T - 1) / T;        // 16-lanes-per-node (agg2)

    k_front<<<GB + GN, T>>>(src, dst, x, W1, asr1, adst1);
    k_agg1<<<gW1, T>>>(W1, b1, W2, asr2, adst2);
    k_agg2<<<gW2, T>>>(b2, out);
}